// round 11
// baseline (speedup 1.0000x reference)
#include <cuda_runtime.h>
#include <cuda_fp16.h>

#define N_NODES 50000
#define N_EDGES 50000
#define CIN 256
#define COUT 128
#define MAXE 1600000
#define SCAN_CHUNK 2048
#define SCAN_BLOCKS 25   // ceil(50000/2048)

#define GEMM_BLOCKS 391  // ceil(50000/128)
#define CNT_BLOCKS 512
#define FILL_BLOCKS_PER_VIEW 512

// ---------------- scratch (static device globals; ~50 MB total) ----------------
__device__ __align__(16) __half g_x[(size_t)N_NODES * COUT];        // 12.8 MB
__device__ __align__(16) __half g_edge[2][(size_t)N_EDGES * COUT];  // 25.6 MB
__device__ int g_ecnt[2][N_EDGES];                                  // count -> fill cursor
__device__ int g_ncnt[2][N_NODES];
__device__ int g_eoff[2][N_EDGES + 1];
__device__ int g_noff[2][N_NODES + 1];
__device__ unsigned short g_eadj[2][MAXE];                          // node ids by edge
__device__ unsigned short g_nadj[2][MAXE];                          // edge ids by node
__device__ int g_part[4][SCAN_BLOCKS];

__device__ __forceinline__ void sel_arr(int a, int*& cnt, int*& off) {
    if (a == 0)      { cnt = g_ecnt[0]; off = g_eoff[0]; }
    else if (a == 1) { cnt = g_ecnt[1]; off = g_eoff[1]; }
    else if (a == 2) { cnt = g_ncnt[0]; off = g_noff[0]; }
    else             { cnt = g_ncnt[1]; off = g_noff[1]; }
}

__device__ __forceinline__ unsigned int f2tf32(float f) {
    unsigned int r;
    asm("cvt.rna.tf32.f32 %0, %1;" : "=r"(r) : "f"(f));
    return r;
}

// half-warp row accumulate: lane covers 8 halves (16 B) of a 256 B row.
__device__ __forceinline__ void acc_row8(const __half* __restrict__ src, size_t rowbase,
                                         int sl, float* acc) {
    uint4 raw = *reinterpret_cast<const uint4*>(&src[rowbase + sl * 8]);
    float2 f0 = __half22float2(*reinterpret_cast<__half2*>(&raw.x));
    float2 f1 = __half22float2(*reinterpret_cast<__half2*>(&raw.y));
    float2 f2 = __half22float2(*reinterpret_cast<__half2*>(&raw.z));
    float2 f3 = __half22float2(*reinterpret_cast<__half2*>(&raw.w));
    acc[0] += f0.x; acc[1] += f0.y; acc[2] += f1.x; acc[3] += f1.y;
    acc[4] += f2.x; acc[5] += f2.y; acc[6] += f3.x; acc[7] += f3.y;
}

// ---------------- K0: zero counters only ----------------
__global__ void zero_kernel() {
    int i = blockIdx.x * blockDim.x + threadIdx.x;
    if (i < N_EDGES) { g_ecnt[0][i] = 0; g_ecnt[1][i] = 0; }
    if (i < N_NODES) { g_ncnt[0][i] = 0; g_ncnt[1][i] = 0; }
}

// ---------------- K1: GEMM [0,391) + count [391,903) + copy [903,...) ----------
__global__ void __launch_bounds__(256) gemm_count_copy_kernel(
        const float* __restrict__ A, const float* __restrict__ W,
        const int* __restrict__ av, const int* __restrict__ ab, int E,
        const float* __restrict__ category, const float* __restrict__ av_feat,
        float* __restrict__ out, int cat_elems, int av_elems) {

    if (blockIdx.x >= GEMM_BLOCKS + CNT_BLOCKS) {
        const int tot4 = (cat_elems + av_elems) >> 2;
        int i = (blockIdx.x - GEMM_BLOCKS - CNT_BLOCKS) * 256 + threadIdx.x;
        if (i < tot4) {
            const int cat4 = cat_elems >> 2;
            float4 v;
            if (i < cat4) v = reinterpret_cast<const float4*>(category)[i];
            else          v = reinterpret_cast<const float4*>(av_feat)[i - cat4];
            reinterpret_cast<float4*>(out + (size_t)N_NODES * COUT)[i] = v;
        }
        return;
    }
    if (blockIdx.x >= GEMM_BLOCKS) {
        const int stride = CNT_BLOCKS * 256;
        for (int i = (blockIdx.x - GEMM_BLOCKS) * 256 + threadIdx.x; i < E; i += stride) {
            atomicAdd(&g_ncnt[0][__ldg(&av[i])], 1);
            atomicAdd(&g_ecnt[0][__ldg(&av[E + i])], 1);
            atomicAdd(&g_ncnt[1][__ldg(&ab[i])], 1);
            atomicAdd(&g_ecnt[1][__ldg(&ab[E + i])], 1);
        }
        return;
    }

    // ---- GEMM path ----
    __shared__ __align__(16) float As[128][20];
    __shared__ __align__(16) float Bs[16][136];

    const int tid = threadIdx.x;
    const int lane = tid & 31;
    const int warp = tid >> 5;
    const int m0 = blockIdx.x * 128;
    const int wm = (warp >> 1) * 32;
    const int wn = (warp & 1) * 64;
    const int r4 = lane >> 2;
    const int q4 = lane & 3;

    float c[2][8][4];
#pragma unroll
    for (int ma = 0; ma < 2; ma++)
#pragma unroll
        for (int na = 0; na < 8; na++)
#pragma unroll
            for (int i = 0; i < 4; i++) c[ma][na][i] = 0.0f;

    for (int k0 = 0; k0 < CIN; k0 += 16) {
#pragma unroll
        for (int l = 0; l < 2; l++) {
            int f = tid * 2 + l;
            int arow = f >> 2, aq = f & 3;
            float4 avv = make_float4(0.f, 0.f, 0.f, 0.f);
            if (m0 + arow < N_NODES)
                avv = *reinterpret_cast<const float4*>(&A[(size_t)(m0 + arow) * CIN + k0 + aq * 4]);
            *reinterpret_cast<float4*>(&As[arow][aq * 4]) = avv;
            int brow = f >> 5, bc = f & 31;
            *reinterpret_cast<float4*>(&Bs[brow][bc * 4]) =
                *reinterpret_cast<const float4*>(&W[(size_t)(k0 + brow) * COUT + bc * 4]);
        }
        __syncthreads();

#pragma unroll
        for (int ka = 0; ka < 2; ka++) {
            const int kb = ka * 8;
            unsigned int a[2][4], b[8][2];
#pragma unroll
            for (int ma = 0; ma < 2; ma++) {
                const int mrow = wm + ma * 16 + r4;
                a[ma][0] = f2tf32(As[mrow][kb + q4]);
                a[ma][1] = f2tf32(As[mrow + 8][kb + q4]);
                a[ma][2] = f2tf32(As[mrow][kb + q4 + 4]);
                a[ma][3] = f2tf32(As[mrow + 8][kb + q4 + 4]);
            }
#pragma unroll
            for (int na = 0; na < 8; na++) {
                const int ncol = wn + na * 8 + r4;
                b[na][0] = f2tf32(Bs[kb + q4][ncol]);
                b[na][1] = f2tf32(Bs[kb + q4 + 4][ncol]);
            }
#pragma unroll
            for (int ma = 0; ma < 2; ma++)
#pragma unroll
                for (int na = 0; na < 8; na++) {
                    asm volatile(
                        "mma.sync.aligned.m16n8k8.row.col.f32.tf32.tf32.f32 "
                        "{%0,%1,%2,%3}, {%4,%5,%6,%7}, {%8,%9}, {%0,%1,%2,%3};"
                        : "+f"(c[ma][na][0]), "+f"(c[ma][na][1]),
                          "+f"(c[ma][na][2]), "+f"(c[ma][na][3])
                        : "r"(a[ma][0]), "r"(a[ma][1]), "r"(a[ma][2]), "r"(a[ma][3]),
                          "r"(b[na][0]), "r"(b[na][1]));
                }
        }
        __syncthreads();
    }

#pragma unroll
    for (int ma = 0; ma < 2; ma++) {
        const int row0 = m0 + wm + ma * 16 + r4;
        const int row1 = row0 + 8;
#pragma unroll
        for (int na = 0; na < 8; na++) {
            const int col = wn + na * 8 + q4 * 2;
            if (row0 < N_NODES) {
                __half2 h = __floats2half2_rn(c[ma][na][0], c[ma][na][1]);
                *reinterpret_cast<__half2*>(&g_x[(size_t)row0 * COUT + col]) = h;
            }
            if (row1 < N_NODES) {
                __half2 h = __floats2half2_rn(c[ma][na][2], c[ma][na][3]);
                *reinterpret_cast<__half2*>(&g_x[(size_t)row1 * COUT + col]) = h;
            }
        }
    }
}

// ---------------- scan: 3 phases ----------------
__global__ void __launch_bounds__(256) scan_part_kernel() {
    int* cnt; int* off;
    sel_arr(blockIdx.y, cnt, off);
    const int base = blockIdx.x * SCAN_CHUNK;
    const int tid = threadIdx.x;
    int sum = 0;
#pragma unroll
    for (int j = 0; j < 8; j++) {
        int i = base + j * 256 + tid;
        if (i < 50000) sum += cnt[i];
    }
#pragma unroll
    for (int d = 16; d > 0; d >>= 1) sum += __shfl_down_sync(0xffffffffu, sum, d);
    __shared__ int ws[8];
    if ((tid & 31) == 0) ws[tid >> 5] = sum;
    __syncthreads();
    if (tid == 0) {
        int t = 0;
#pragma unroll
        for (int w = 0; w < 8; w++) t += ws[w];
        g_part[blockIdx.y][blockIdx.x] = t;
    }
}

__global__ void __launch_bounds__(128) scan_part2_kernel() {
    const int w = threadIdx.x >> 5, lane = threadIdx.x & 31;
    int v = (lane < SCAN_BLOCKS) ? g_part[w][lane] : 0;
    int s = v;
#pragma unroll
    for (int d = 1; d < 32; d <<= 1) {
        int t = __shfl_up_sync(0xffffffffu, s, d);
        if (lane >= d) s += t;
    }
    if (lane < SCAN_BLOCKS) g_part[w][lane] = s - v;
    if (lane == SCAN_BLOCKS - 1) {
        int* cnt; int* off;
        sel_arr(w, cnt, off);
        off[50000] = s;
    }
}

__global__ void __launch_bounds__(256) scan_emit_kernel() {
    __shared__ int sh[SCAN_CHUNK];
    __shared__ int ws[8];
    int* cnt; int* off;
    sel_arr(blockIdx.y, cnt, off);
    const int base = blockIdx.x * SCAN_CHUNK;
    const int tid = threadIdx.x;
    const int lane = tid & 31, wid = tid >> 5;

#pragma unroll
    for (int j = 0; j < 8; j++) {
        int i = base + j * 256 + tid;
        sh[j * 256 + tid] = (i < 50000) ? cnt[i] : 0;
    }
    __syncthreads();

    int loc[8];
    int tsum = 0;
    const int t0 = tid * 8;
#pragma unroll
    for (int j = 0; j < 8; j++) { loc[j] = tsum; tsum += sh[t0 + j]; }

    int s = tsum;
#pragma unroll
    for (int d = 1; d < 32; d <<= 1) {
        int t = __shfl_up_sync(0xffffffffu, s, d);
        if (lane >= d) s += t;
    }
    if (lane == 31) ws[wid] = s;
    __syncthreads();
    int wpre = 0;
#pragma unroll
    for (int w = 0; w < 7; w++) if (w < wid) wpre += ws[w];
    const int tpre = s - tsum + wpre + g_part[blockIdx.y][blockIdx.x];
    __syncthreads();

#pragma unroll
    for (int j = 0; j < 8; j++) sh[t0 + j] = tpre + loc[j];
    __syncthreads();

#pragma unroll
    for (int j = 0; j < 8; j++) {
        int i = base + j * 256 + tid;
        if (i < 50000) { int v = sh[j * 256 + tid]; off[i] = v; cnt[i] = v; }
    }
}

// ---------------- K5: fill both views (block-partitioned) -----------------------
__global__ void __launch_bounds__(256) fill2_kernel(const int* __restrict__ av,
                                                    const int* __restrict__ ab, int E) {
    const int view = (blockIdx.x >= FILL_BLOCKS_PER_VIEW) ? 1 : 0;
    const int* idx = view ? ab : av;
    int* ecur = g_ecnt[view];
    int* ncur = g_ncnt[view];
    unsigned short* eadj = g_eadj[view];
    unsigned short* nadj = g_nadj[view];
    const int b0 = blockIdx.x - view * FILL_BLOCKS_PER_VIEW;
    const int stride = FILL_BLOCKS_PER_VIEW * 256;
    for (int i = b0 * 256 + threadIdx.x; i < E; i += stride) {
        int n = __ldg(&idx[i]), e = __ldg(&idx[E + i]);
        eadj[atomicAdd(&ecur[e], 1)] = (unsigned short)n;
        nadj[atomicAdd(&ncur[n], 1)] = (unsigned short)e;
    }
}

// ---------------- K6: n2e both views — half-warp per row, 4 rows in flight ------
__global__ void __launch_bounds__(256) n2e2_kernel() {
    const int gw = (blockIdx.x * blockDim.x + threadIdx.x) >> 5;
    if (gw >= 2 * N_EDGES) return;
    const int view = (gw >= N_EDGES) ? 1 : 0;
    const int e = gw - view * N_EDGES;
    const int lane = threadIdx.x & 31;
    const int h = lane >> 4;          // half-warp id (0/1)
    const int sl = lane & 15;         // sub-lane: 8 halves (16 B) of the row
    const int base = g_eoff[view][e], end = g_eoff[view][e + 1];
    const unsigned short* __restrict__ eadj = g_eadj[view];

    float acc0[8] = {0,0,0,0,0,0,0,0};
    float acc1[8] = {0,0,0,0,0,0,0,0};
    for (int j0 = base; j0 < end; j0 += 32) {
        const int cnt = min(32, end - j0);
        const int myid = (lane < cnt) ? (int)eadj[j0 + lane] : 0;
        int t = 0;
        for (; t + 4 <= cnt; t += 4) {
            const int idA = __shfl_sync(0xffffffffu, myid, t + h);
            const int idB = __shfl_sync(0xffffffffu, myid, t + 2 + h);
            acc_row8(g_x, (size_t)idA * COUT, sl, acc0);
            acc_row8(g_x, (size_t)idB * COUT, sl, acc1);
        }
        for (; t + 2 <= cnt; t += 2) {
            const int idA = __shfl_sync(0xffffffffu, myid, t + h);
            acc_row8(g_x, (size_t)idA * COUT, sl, acc0);
        }
        if (t < cnt) {
            const int idA = __shfl_sync(0xffffffffu, myid, t);
            if (h == 0) acc_row8(g_x, (size_t)idA * COUT, sl, acc0);
        }
    }
#pragma unroll
    for (int k = 0; k < 8; k++) {
        acc0[k] += acc1[k];
        acc0[k] += __shfl_xor_sync(0xffffffffu, acc0[k], 16);
    }
    const float s = (end > base) ? __fdividef(1.f, (float)(end - base)) : 0.f;
    if (h == 0) {
        __half2 h0 = __floats2half2_rn(acc0[0] * s, acc0[1] * s);
        __half2 h1 = __floats2half2_rn(acc0[2] * s, acc0[3] * s);
        __half2 h2 = __floats2half2_rn(acc0[4] * s, acc0[5] * s);
        __half2 h3 = __floats2half2_rn(acc0[6] * s, acc0[7] * s);
        uint4 o;
        o.x = *reinterpret_cast<unsigned int*>(&h0);
        o.y = *reinterpret_cast<unsigned int*>(&h1);
        o.z = *reinterpret_cast<unsigned int*>(&h2);
        o.w = *reinterpret_cast<unsigned int*>(&h3);
        *reinterpret_cast<uint4*>(&g_edge[view][(size_t)e * COUT + sl * 8]) = o;
    }
}

// ---------------- K7: e2n fused — half-warp per row, 4 rows in flight -----------
__global__ void __launch_bounds__(256) e2n_kernel(const float* __restrict__ bias,
                                                  float* __restrict__ out) {
    const int n = (blockIdx.x * blockDim.x + threadIdx.x) >> 5;
    if (n >= N_NODES) return;
    const int lane = threadIdx.x & 31;
    const int h = lane >> 4;
    const int sl = lane & 15;

    float r[8];
#pragma unroll
    for (int k = 0; k < 8; k++) r[k] = bias[sl * 8 + k];

#pragma unroll
    for (int v = 0; v < 2; v++) {
        const int base = g_noff[v][n], end = g_noff[v][n + 1];
        const __half* __restrict__ esrc = g_edge[v];
        const unsigned short* __restrict__ nadj = g_nadj[v];
        float acc0[8] = {0,0,0,0,0,0,0,0};
        float acc1[8] = {0,0,0,0,0,0,0,0};
        for (int j0 = base; j0 < end; j0 += 32) {
            const int cnt = min(32, end - j0);
            const int myid = (lane < cnt) ? (int)nadj[j0 + lane] : 0;
            int t = 0;
            for (; t + 4 <= cnt; t += 4) {
                const int idA = __shfl_sync(0xffffffffu, myid, t + h);
                const int idB = __shfl_sync(0xffffffffu, myid, t + 2 + h);
                acc_row8(esrc, (size_t)idA * COUT, sl, acc0);
                acc_row8(esrc, (size_t)idB * COUT, sl, acc1);
            }
            for (; t + 2 <= cnt; t += 2) {
                const int idA = __shfl_sync(0xffffffffu, myid, t + h);
                acc_row8(esrc, (size_t)idA * COUT, sl, acc0);
            }
            if (t < cnt) {
                const int idA = __shfl_sync(0xffffffffu, myid, t);
                if (h == 0) acc_row8(esrc, (size_t)idA * COUT, sl, acc0);
            }
        }
        const float c = (end > base) ? __fdividef(0.5f, (float)(end - base)) : 0.f;
#pragma unroll
        for (int k = 0; k < 8; k++) {
            acc0[k] += acc1[k];
            acc0[k] += __shfl_xor_sync(0xffffffffu, acc0[k], 16);
            r[k] += c * acc0[k];
        }
    }
    if (h == 0) {
        float4 v0 = make_float4(r[0], r[1], r[2], r[3]);
        float4 v1 = make_float4(r[4], r[5], r[6], r[7]);
        *reinterpret_cast<float4*>(&out[(size_t)n * COUT + sl * 8]) = v0;
        *reinterpret_cast<float4*>(&out[(size_t)n * COUT + sl * 8 + 4]) = v1;
    }
}

// ---------------- launcher ----------------
extern "C" void kernel_launch(void* const* d_in, const int* in_sizes, int n_in,
                              void* d_out, int out_size) {
    const float* product  = (const float*)d_in[0];
    const float* category = (const float*)d_in[1];
    const float* av_feat  = (const float*)d_in[2];
    const int* also_view  = (const int*)d_in[3];   // int32
    const int* also_buy   = (const int*)d_in[4];
    const float* lin_w    = (const float*)d_in[5];
    const float* bias     = (const float*)d_in[6];
    float* out = (float*)d_out;

    const int E = in_sizes[3] / 2;
    const int cat_elems = in_sizes[1];
    const int av_elems = in_sizes[2];

    // K0: zero counters (must precede count)
    zero_kernel<<<(N_EDGES + 255) / 256, 256>>>();

    // K1: GEMM + count + passthrough copies, one wave
    const int CPB = (((cat_elems + av_elems) >> 2) + 255) / 256;
    gemm_count_copy_kernel<<<GEMM_BLOCKS + CNT_BLOCKS + CPB, 256>>>(
        product, lin_w, also_view, also_buy, E,
        category, av_feat, out, cat_elems, av_elems);

    // scan (3 small kernels)
    scan_part_kernel<<<dim3(SCAN_BLOCKS, 4), 256>>>();
    scan_part2_kernel<<<1, 128>>>();
    scan_emit_kernel<<<dim3(SCAN_BLOCKS, 4), 256>>>();

    // K5: fill both views
    fill2_kernel<<<2 * FILL_BLOCKS_PER_VIEW, 256>>>(also_view, also_buy, E);

    // K6: n2e both views
    n2e2_kernel<<<(2 * N_EDGES * 32 + 255) / 256, 256>>>();

    // K7: e2n fused
    e2n_kernel<<<(N_NODES * 32 + 255) / 256, 256>>>(bias, out);
}

// round 12
// speedup vs baseline: 1.0053x; 1.0053x over previous
#include <cuda_runtime.h>
#include <cuda_fp16.h>

#define N_NODES 50000
#define N_EDGES 50000
#define CIN 256
#define COUT 128
#define MAXE 1600000
#define SCAN_CHUNK 2048
#define SCAN_BLOCKS 25   // ceil(50000/2048)

#define GEMM_BLOCKS 391  // ceil(50000/128)
#define CNT_BLOCKS 2048
#define FILL_BLOCKS_PER_VIEW 512

// ---------------- scratch (static device globals; ~50 MB total) ----------------
__device__ __align__(16) __half g_x[(size_t)N_NODES * COUT];        // 12.8 MB
__device__ __align__(16) __half g_edge[2][(size_t)N_EDGES * COUT];  // 25.6 MB
__device__ int g_ecnt[2][N_EDGES];                                  // count -> fill cursor
__device__ int g_ncnt[2][N_NODES];
__device__ int g_eoff[2][N_EDGES + 1];
__device__ int g_noff[2][N_NODES + 1];
__device__ unsigned short g_eadj[2][MAXE];                          // node ids by edge
__device__ unsigned short g_nadj[2][MAXE];                          // edge ids by node
__device__ int g_part[4][SCAN_BLOCKS];

__device__ __forceinline__ void sel_arr(int a, int*& cnt, int*& off) {
    if (a == 0)      { cnt = g_ecnt[0]; off = g_eoff[0]; }
    else if (a == 1) { cnt = g_ecnt[1]; off = g_eoff[1]; }
    else if (a == 2) { cnt = g_ncnt[0]; off = g_noff[0]; }
    else             { cnt = g_ncnt[1]; off = g_noff[1]; }
}

__device__ __forceinline__ unsigned int f2tf32(float f) {
    unsigned int r;
    asm("cvt.rna.tf32.f32 %0, %1;" : "=r"(r) : "f"(f));
    return r;
}

// fp16 row accumulate (full warp, uint2 per lane = 256 B row)
__device__ __forceinline__ void acc_row(const __half* __restrict__ src, size_t rowbase,
                                        int lane, float4& acc) {
    uint2 raw = *reinterpret_cast<const uint2*>(&src[rowbase + lane * 4]);
    float2 f0 = __half22float2(*reinterpret_cast<__half2*>(&raw.x));
    float2 f1 = __half22float2(*reinterpret_cast<__half2*>(&raw.y));
    acc.x += f0.x; acc.y += f0.y; acc.z += f1.x; acc.w += f1.y;
}

// ---------------- K0: zero counters + passthrough copies ------------------------
__global__ void __launch_bounds__(256) zero_copy_kernel(const float* __restrict__ category,
                                                        const float* __restrict__ av_feat,
                                                        float* __restrict__ out,
                                                        int cat_elems, int av_elems) {
    const int ZB = (N_EDGES + 255) / 256;
    int bid = blockIdx.x;
    if (bid < ZB) {
        int i = bid * 256 + threadIdx.x;
        if (i < N_EDGES) { g_ecnt[0][i] = 0; g_ecnt[1][i] = 0; }
        if (i < N_NODES) { g_ncnt[0][i] = 0; g_ncnt[1][i] = 0; }
    } else {
        const int tot4 = (cat_elems + av_elems) >> 2;
        int i = (bid - ZB) * 256 + threadIdx.x;
        if (i < tot4) {
            const int cat4 = cat_elems >> 2;
            float4 v;
            if (i < cat4) v = reinterpret_cast<const float4*>(category)[i];
            else          v = reinterpret_cast<const float4*>(av_feat)[i - cat4];
            reinterpret_cast<float4*>(out + (size_t)N_NODES * COUT)[i] = v;
        }
    }
}

// ---------------- K1: count (standalone, full chip) -----------------------------
__global__ void __launch_bounds__(256) count_kernel(const int* __restrict__ av,
                                                    const int* __restrict__ ab, int E) {
    const int stride = CNT_BLOCKS * 256;
    for (int i = blockIdx.x * 256 + threadIdx.x; i < E; i += stride) {
        atomicAdd(&g_ncnt[0][__ldg(&av[i])], 1);
        atomicAdd(&g_ecnt[0][__ldg(&av[E + i])], 1);
        atomicAdd(&g_ncnt[1][__ldg(&ab[i])], 1);
        atomicAdd(&g_ecnt[1][__ldg(&ab[E + i])], 1);
    }
}

// ---------------- K2: per-chunk partial sums ------------------------------------
__global__ void __launch_bounds__(256) scan_part_kernel() {
    int* cnt; int* off;
    sel_arr(blockIdx.y, cnt, off);
    const int base = blockIdx.x * SCAN_CHUNK;
    const int tid = threadIdx.x;
    int sum = 0;
#pragma unroll
    for (int j = 0; j < 8; j++) {
        int i = base + j * 256 + tid;
        if (i < 50000) sum += cnt[i];
    }
#pragma unroll
    for (int d = 16; d > 0; d >>= 1) sum += __shfl_down_sync(0xffffffffu, sum, d);
    __shared__ int ws[8];
    if ((tid & 31) == 0) ws[tid >> 5] = sum;
    __syncthreads();
    if (tid == 0) {
        int t = 0;
#pragma unroll
        for (int w = 0; w < 8; w++) t += ws[w];
        g_part[blockIdx.y][blockIdx.x] = t;
    }
}

// ---------------- K3: emit off[] + cursor (inlines cross-chunk prefix) ----------
__global__ void __launch_bounds__(256) scan_emit_kernel() {
    __shared__ int sh[SCAN_CHUNK];
    __shared__ int ws[8];
    __shared__ int blockpre_s, total_s;
    int* cnt; int* off;
    sel_arr(blockIdx.y, cnt, off);
    const int base = blockIdx.x * SCAN_CHUNK;
    const int tid = threadIdx.x;
    const int lane = tid & 31, wid = tid >> 5;

    // warp 0: prefix of partials for this chunk + grand total
    if (wid == 0) {
        int p = (lane < SCAN_BLOCKS) ? g_part[blockIdx.y][lane] : 0;
        int pre = (lane < blockIdx.x) ? p : 0;
        int tot = p;
#pragma unroll
        for (int d = 16; d > 0; d >>= 1) {
            pre += __shfl_down_sync(0xffffffffu, pre, d);
            tot += __shfl_down_sync(0xffffffffu, tot, d);
        }
        if (lane == 0) { blockpre_s = pre; total_s = tot; }
    }

#pragma unroll
    for (int j = 0; j < 8; j++) {
        int i = base + j * 256 + tid;
        sh[j * 256 + tid] = (i < 50000) ? cnt[i] : 0;
    }
    __syncthreads();

    int loc[8];
    int tsum = 0;
    const int t0 = tid * 8;
#pragma unroll
    for (int j = 0; j < 8; j++) { loc[j] = tsum; tsum += sh[t0 + j]; }

    int s = tsum;
#pragma unroll
    for (int d = 1; d < 32; d <<= 1) {
        int t = __shfl_up_sync(0xffffffffu, s, d);
        if (lane >= d) s += t;
    }
    if (lane == 31) ws[wid] = s;
    __syncthreads();
    int wpre = 0;
#pragma unroll
    for (int w = 0; w < 7; w++) if (w < wid) wpre += ws[w];
    const int tpre = s - tsum + wpre + blockpre_s;
    __syncthreads();

#pragma unroll
    for (int j = 0; j < 8; j++) sh[t0 + j] = tpre + loc[j];
    __syncthreads();

#pragma unroll
    for (int j = 0; j < 8; j++) {
        int i = base + j * 256 + tid;
        if (i < 50000) { int v = sh[j * 256 + tid]; off[i] = v; cnt[i] = v; }
    }
    if (blockIdx.x == SCAN_BLOCKS - 1 && tid == 0) off[50000] = total_s;
}

// ---------------- K4: GEMM [0,391) + fill [391, 391+1024) -----------------------
__global__ void __launch_bounds__(256) gemm_fill_kernel(
        const float* __restrict__ A, const float* __restrict__ W,
        const int* __restrict__ av, const int* __restrict__ ab, int E) {

    if (blockIdx.x >= GEMM_BLOCKS) {
        // ---- fill path (both views) ----
        const int fb = blockIdx.x - GEMM_BLOCKS;                 // 0..1023
        const int view = (fb >= FILL_BLOCKS_PER_VIEW) ? 1 : 0;
        const int* idx = view ? ab : av;
        int* ecur = g_ecnt[view];
        int* ncur = g_ncnt[view];
        unsigned short* eadj = g_eadj[view];
        unsigned short* nadj = g_nadj[view];
        const int b0 = fb - view * FILL_BLOCKS_PER_VIEW;
        const int stride = FILL_BLOCKS_PER_VIEW * 256;
        for (int i = b0 * 256 + threadIdx.x; i < E; i += stride) {
            int n = __ldg(&idx[i]), e = __ldg(&idx[E + i]);
            eadj[atomicAdd(&ecur[e], 1)] = (unsigned short)n;
            nadj[atomicAdd(&ncur[n], 1)] = (unsigned short)e;
        }
        return;
    }

    // ---- GEMM path ----
    __shared__ __align__(16) float As[128][20];
    __shared__ __align__(16) float Bs[16][136];

    const int tid = threadIdx.x;
    const int lane = tid & 31;
    const int warp = tid >> 5;
    const int m0 = blockIdx.x * 128;
    const int wm = (warp >> 1) * 32;
    const int wn = (warp & 1) * 64;
    const int r4 = lane >> 2;
    const int q4 = lane & 3;

    float c[2][8][4];
#pragma unroll
    for (int ma = 0; ma < 2; ma++)
#pragma unroll
        for (int na = 0; na < 8; na++)
#pragma unroll
            for (int i = 0; i < 4; i++) c[ma][na][i] = 0.0f;

    for (int k0 = 0; k0 < CIN; k0 += 16) {
#pragma unroll
        for (int l = 0; l < 2; l++) {
            int f = tid * 2 + l;
            int arow = f >> 2, aq = f & 3;
            float4 avv = make_float4(0.f, 0.f, 0.f, 0.f);
            if (m0 + arow < N_NODES)
                avv = *reinterpret_cast<const float4*>(&A[(size_t)(m0 + arow) * CIN + k0 + aq * 4]);
            *reinterpret_cast<float4*>(&As[arow][aq * 4]) = avv;
            int brow = f >> 5, bc = f & 31;
            *reinterpret_cast<float4*>(&Bs[brow][bc * 4]) =
                *reinterpret_cast<const float4*>(&W[(size_t)(k0 + brow) * COUT + bc * 4]);
        }
        __syncthreads();

#pragma unroll
        for (int ka = 0; ka < 2; ka++) {
            const int kb = ka * 8;
            unsigned int a[2][4], b[8][2];
#pragma unroll
            for (int ma = 0; ma < 2; ma++) {
                const int mrow = wm + ma * 16 + r4;
                a[ma][0] = f2tf32(As[mrow][kb + q4]);
                a[ma][1] = f2tf32(As[mrow + 8][kb + q4]);
                a[ma][2] = f2tf32(As[mrow][kb + q4 + 4]);
                a[ma][3] = f2tf32(As[mrow + 8][kb + q4 + 4]);
            }
#pragma unroll
            for (int na = 0; na < 8; na++) {
                const int ncol = wn + na * 8 + r4;
                b[na][0] = f2tf32(Bs[kb + q4][ncol]);
                b[na][1] = f2tf32(Bs[kb + q4 + 4][ncol]);
            }
#pragma unroll
            for (int ma = 0; ma < 2; ma++)
#pragma unroll
                for (int na = 0; na < 8; na++) {
                    asm volatile(
                        "mma.sync.aligned.m16n8k8.row.col.f32.tf32.tf32.f32 "
                        "{%0,%1,%2,%3}, {%4,%5,%6,%7}, {%8,%9}, {%0,%1,%2,%3};"
                        : "+f"(c[ma][na][0]), "+f"(c[ma][na][1]),
                          "+f"(c[ma][na][2]), "+f"(c[ma][na][3])
                        : "r"(a[ma][0]), "r"(a[ma][1]), "r"(a[ma][2]), "r"(a[ma][3]),
                          "r"(b[na][0]), "r"(b[na][1]));
                }
        }
        __syncthreads();
    }

#pragma unroll
    for (int ma = 0; ma < 2; ma++) {
        const int row0 = m0 + wm + ma * 16 + r4;
        const int row1 = row0 + 8;
#pragma unroll
        for (int na = 0; na < 8; na++) {
            const int col = wn + na * 8 + q4 * 2;
            if (row0 < N_NODES) {
                __half2 h = __floats2half2_rn(c[ma][na][0], c[ma][na][1]);
                *reinterpret_cast<__half2*>(&g_x[(size_t)row0 * COUT + col]) = h;
            }
            if (row1 < N_NODES) {
                __half2 h = __floats2half2_rn(c[ma][na][2], c[ma][na][3]);
                *reinterpret_cast<__half2*>(&g_x[(size_t)row1 * COUT + col]) = h;
            }
        }
    }
}

// ---------------- K5: n2e both views (warp per row, 2-way ILP) ------------------
__global__ void __launch_bounds__(256) n2e2_kernel() {
    const int gw = (blockIdx.x * blockDim.x + threadIdx.x) >> 5;
    if (gw >= 2 * N_EDGES) return;
    const int view = (gw >= N_EDGES) ? 1 : 0;
    const int e = gw - view * N_EDGES;
    const int lane = threadIdx.x & 31;
    const int base = g_eoff[view][e], end = g_eoff[view][e + 1];
    const unsigned short* __restrict__ eadj = g_eadj[view];

    float4 acc0 = make_float4(0.f, 0.f, 0.f, 0.f);
    float4 acc1 = make_float4(0.f, 0.f, 0.f, 0.f);
    for (int j0 = base; j0 < end; j0 += 32) {
        const int cnt = min(32, end - j0);
        const int myid = (lane < cnt) ? (int)eadj[j0 + lane] : 0;
        int t = 0;
        for (; t + 2 <= cnt; t += 2) {
            const int id0 = __shfl_sync(0xffffffffu, myid, t);
            const int id1 = __shfl_sync(0xffffffffu, myid, t + 1);
            acc_row(g_x, (size_t)id0 * COUT, lane, acc0);
            acc_row(g_x, (size_t)id1 * COUT, lane, acc1);
        }
        if (t < cnt) {
            const int id0 = __shfl_sync(0xffffffffu, myid, t);
            acc_row(g_x, (size_t)id0 * COUT, lane, acc0);
        }
    }
    acc0.x += acc1.x; acc0.y += acc1.y; acc0.z += acc1.z; acc0.w += acc1.w;
    const float s = (end > base) ? __fdividef(1.f, (float)(end - base)) : 0.f;
    __half2 h0 = __floats2half2_rn(acc0.x * s, acc0.y * s);
    __half2 h1 = __floats2half2_rn(acc0.z * s, acc0.w * s);
    uint2 o;
    o.x = *reinterpret_cast<unsigned int*>(&h0);
    o.y = *reinterpret_cast<unsigned int*>(&h1);
    *reinterpret_cast<uint2*>(&g_edge[view][(size_t)e * COUT + lane * 4]) = o;
}

// ---------------- K6: e2n fused (both views + bias, 2-way ILP) ------------------
__global__ void __launch_bounds__(256) e2n_kernel(const float* __restrict__ bias,
                                                  float* __restrict__ out) {
    const int n = (blockIdx.x * blockDim.x + threadIdx.x) >> 5;
    if (n >= N_NODES) return;
    const int lane = threadIdx.x & 31;

    float4 r = *reinterpret_cast<const float4*>(&bias[lane * 4]);
#pragma unroll
    for (int v = 0; v < 2; v++) {
        const int base = g_noff[v][n], end = g_noff[v][n + 1];
        const __half* __restrict__ esrc = g_edge[v];
        const unsigned short* __restrict__ nadj = g_nadj[v];
        float4 acc0 = make_float4(0.f, 0.f, 0.f, 0.f);
        float4 acc1 = make_float4(0.f, 0.f, 0.f, 0.f);
        for (int j0 = base; j0 < end; j0 += 32) {
            const int cnt = min(32, end - j0);
            const int myid = (lane < cnt) ? (int)nadj[j0 + lane] : 0;
            int t = 0;
            for (; t + 2 <= cnt; t += 2) {
                const int id0 = __shfl_sync(0xffffffffu, myid, t);
                const int id1 = __shfl_sync(0xffffffffu, myid, t + 1);
                acc_row(esrc, (size_t)id0 * COUT, lane, acc0);
                acc_row(esrc, (size_t)id1 * COUT, lane, acc1);
            }
            if (t < cnt) {
                const int id0 = __shfl_sync(0xffffffffu, myid, t);
                acc_row(esrc, (size_t)id0 * COUT, lane, acc0);
            }
        }
        acc0.x += acc1.x; acc0.y += acc1.y; acc0.z += acc1.z; acc0.w += acc1.w;
        const float c = (end > base) ? __fdividef(0.5f, (float)(end - base)) : 0.f;
        r.x += c * acc0.x; r.y += c * acc0.y; r.z += c * acc0.z; r.w += c * acc0.w;
    }
    *reinterpret_cast<float4*>(&out[(size_t)n * COUT + lane * 4]) = r;
}

// ---------------- launcher ----------------
extern "C" void kernel_launch(void* const* d_in, const int* in_sizes, int n_in,
                              void* d_out, int out_size) {
    const float* product  = (const float*)d_in[0];
    const float* category = (const float*)d_in[1];
    const float* av_feat  = (const float*)d_in[2];
    const int* also_view  = (const int*)d_in[3];   // int32
    const int* also_buy   = (const int*)d_in[4];
    const float* lin_w    = (const float*)d_in[5];
    const float* bias     = (const float*)d_in[6];
    float* out = (float*)d_out;

    const int E = in_sizes[3] / 2;
    const int cat_elems = in_sizes[1];
    const int av_elems = in_sizes[2];

    // K0: zero counters + passthrough copies
    const int ZB = (N_EDGES + 255) / 256;
    const int CPB = (((cat_elems + av_elems) >> 2) + 255) / 256;
    zero_copy_kernel<<<ZB + CPB, 256>>>(category, av_feat, out, cat_elems, av_elems);

    // K1: count (standalone)
    count_kernel<<<CNT_BLOCKS, 256>>>(also_view, also_buy, E);

    // K2-K3: scan (2 kernels; emit inlines the partial prefix)
    scan_part_kernel<<<dim3(SCAN_BLOCKS, 4), 256>>>();
    scan_emit_kernel<<<dim3(SCAN_BLOCKS, 4), 256>>>();

    // K4: GEMM + fill, one wave
    gemm_fill_kernel<<<GEMM_BLOCKS + 2 * FILL_BLOCKS_PER_VIEW, 256>>>(
        product, lin_w, also_view, also_buy, E);

    // K5: n2e both views
    n2e2_kernel<<<(2 * N_EDGES * 32 + 255) / 256, 256>>>();

    // K6: e2n fused
    e2n_kernel<<<(N_NODES * 32 + 255) / 256, 256>>>(bias, out);
}